// round 9
// baseline (speedup 1.0000x reference)
#include <cuda_runtime.h>
#include <math.h>

#define B_DIM 64
#define T_DIM 1000
#define P_ORD 10
#define NFRAMES (B_DIM * T_DIM)
#define PI_D 3.14159265358979323846
#define FULLMASK 0xffffffffu

__device__ double d_M[121];
__device__ float d_x0[20];
__device__ float g_pc[10 * NFRAMES];   // transposed: [coef][frame], pc[0]==1 implicit

// Parallel init: one block per matrix entry (j,d); threads split the k-sum.
__global__ void init_consts_kernel() {
    __shared__ double red[128];
    int e = blockIdx.x;
    int j = e / 11, d = e % 11;
    int k = threadIdx.x;

    double term = 0.0;
    if (k >= 1 && k <= 114) {
        double gd = (d == 0) ? 1.0 : 2.0 * cos(2.0 * PI_D * (double)k * (double)d / 512.0);
        term = 2.0 * gd * cos(2.0 * PI_D * (double)k * (double)j / 230.0);
    }
    red[threadIdx.x] = term;
    __syncthreads();
#pragma unroll
    for (int s = 64; s > 0; s >>= 1) {
        if (threadIdx.x < s) red[threadIdx.x] += red[threadIdx.x + s];
        __syncthreads();
    }
    if (threadIdx.x == 0) {
        double s = red[0];
        s += (d == 0) ? 1.0 : 2.0;                               // k = 0 bin
        double g115 = (d == 0) ? 1.0 : 2.0 * cos(2.0 * PI_D * 115.0 * (double)d / 512.0);
        s += ((j & 1) ? -1.0 : 1.0) * g115;                      // k = 115 Nyquist
        d_M[e] = s / 230.0;
    }
    if (e == 0 && threadIdx.x == 127) {
        double cr = 1.0, ci = 0.0;
        for (int p = 0; p < 10; p++) {
            double nr = cr * 0.4 - ci * 0.9;
            double ni = cr * 0.9 + ci * 0.4;
            cr = nr; ci = ni;
            d_x0[p]      = (float)nr;
            d_x0[10 + p] = (float)ni;
        }
    }
}

// ===== Front-end: fp64, one thread per frame, writes pc[1..10] transposed =====
__global__ void frontend_kernel(const float* __restrict__ in) {
    __shared__ double sM[121];
    if (threadIdx.x < 121) sM[threadIdx.x] = d_M[threadIdx.x];
    __syncthreads();

    int frame = blockIdx.x * 128 + threadIdx.x;
    if (frame >= NFRAMES) return;
    int b = frame / T_DIM;
    int t = frame - b * T_DIM;
    const float* base = in + (size_t)b * (P_ORD * T_DIM) + t;

    double A[11];
    A[0] = 1.0;
    {
        double a[10];
        a[0] = (double)base[0];
#pragma unroll
        for (int p = 1; p < 10; p++) {
            double k = (double)base[p * T_DIM];
            double na[10];
#pragma unroll
            for (int i = 0; i < p; i++) na[i] = a[i] + k * a[p - 1 - i];
#pragma unroll
            for (int i = 0; i < p; i++) a[i] = na[i];
            a[p] = k;
        }
#pragma unroll
        for (int i = 0; i < 10; i++) A[i + 1] = a[i];
    }

    double c[11];
#pragma unroll
    for (int d = 0; d < 11; d++) {
        double s = 0.0;
#pragma unroll
        for (int n = 0; n < 11 - d; n++) s = fma(A[n], A[n + d], s);
        c[d] = s;
    }

    double r[11];
#pragma unroll
    for (int j = 0; j < 11; j++) {
        double s = 0.0;
#pragma unroll
        for (int d = 0; d < 11; d++) s = fma(sM[j * 11 + d], c[d], s);
        r[j] = s;
    }

    {
        double a[10];
        double k0 = -r[1] / r[0];
        a[0] = k0;
        double err = r[0] * (1.0 - k0 * k0);
#pragma unroll
        for (int m = 1; m < 10; m++) {
            double acc = r[m + 1];
#pragma unroll
            for (int i = 0; i < m; i++) acc = fma(a[i], r[m - i], acc);
            double k = -acc / err;
            double na[10];
#pragma unroll
            for (int i = 0; i < m; i++) na[i] = a[i] + k * a[m - 1 - i];
#pragma unroll
            for (int i = 0; i < m; i++) a[i] = na[i];
            a[m] = k;
            err *= (1.0 - k * k);
        }
#pragma unroll
        for (int i = 0; i < 10; i++) g_pc[i * NFRAMES + frame] = (float)a[i];
    }
}

// XLA-faithful complex division: Smith + __divsc3-style recovery, IEEE rn.
__device__ __forceinline__ void cdivf(float a, float b, float c, float d,
                                      float& outr, float& outi) {
    float re, im;
    if (fabsf(c) >= fabsf(d)) {
        float r     = __fdiv_rn(d, c);
        float denom = __fadd_rn(c, __fmul_rn(d, r));
        re = __fdiv_rn(__fadd_rn(a, __fmul_rn(b, r)), denom);
        im = __fdiv_rn(__fsub_rn(b, __fmul_rn(a, r)), denom);
    } else {
        float r     = __fdiv_rn(c, d);
        float denom = __fadd_rn(__fmul_rn(c, r), d);
        re = __fdiv_rn(__fadd_rn(__fmul_rn(a, r), b), denom);
        im = __fdiv_rn(__fsub_rn(__fmul_rn(b, r), a), denom);
    }
    if (isnan(re) && isnan(im)) {
        if ((c == 0.0f && d == 0.0f) && (!isnan(a) || !isnan(b))) {
            re = copysignf(INFINITY, c) * a;
            im = copysignf(INFINITY, c) * b;
        } else if ((isinf(a) || isinf(b)) && isfinite(c) && isfinite(d)) {
            float aa = copysignf(isinf(a) ? 1.0f : 0.0f, a);
            float bb = copysignf(isinf(b) ? 1.0f : 0.0f, b);
            re = INFINITY * __fadd_rn(__fmul_rn(aa, c), __fmul_rn(bb, d));
            im = INFINITY * __fsub_rn(__fmul_rn(bb, c), __fmul_rn(aa, d));
        } else if ((isinf(c) || isinf(d)) && isfinite(a) && isfinite(b)) {
            float cc = copysignf(isinf(c) ? 1.0f : 0.0f, c);
            float dd = copysignf(isinf(d) ? 1.0f : 0.0f, d);
            re = 0.0f * __fadd_rn(__fmul_rn(a, cc), __fmul_rn(b, dd));
            im = 0.0f * __fsub_rn(__fmul_rn(b, cc), __fmul_rn(a, dd));
        }
    }
    outr = re; outi = im;
}

// ===== Durand-Kerner: 2 threads per frame, 5 roots each (R5-style exchange) =====
__global__ void __launch_bounds__(256)
dk_kernel(float* __restrict__ out) {
    int gtid  = blockIdx.x * 256 + threadIdx.x;
    int frame = gtid >> 1;
    int half  = gtid & 1;                 // 0: roots 0-4, 1: roots 5-9

    // predictor polynomial (transposed coalesced loads; pc[0] == 1)
    float pc[11];
    pc[0] = 1.0f;
#pragma unroll
    for (int i = 0; i < 10; i++) pc[i + 1] = g_pc[i * NFRAMES + frame];

    float xr[5], xi[5];
#pragma unroll
    for (int i = 0; i < 5; i++) {
        xr[i] = d_x0[half * 5 + i];
        xi[i] = d_x0[10 + half * 5 + i];
    }

#pragma unroll 1
    for (int it = 0; it < 30; it++) {
        // fetch partner's current roots (10 shuffles)
        float pr[5], pimg[5];
#pragma unroll
        for (int j = 0; j < 5; j++) {
            pr[j]   = __shfl_xor_sync(FULLMASK, xr[j], 1);
            pimg[j] = __shfl_xor_sync(FULLMASK, xi[j], 1);
        }
        // global-ordered halves via SELs
        float loR[5], loI[5], hiR[5], hiI[5];
#pragma unroll
        for (int j = 0; j < 5; j++) {
            loR[j] = half ? pr[j]   : xr[j];
            loI[j] = half ? pimg[j] : xi[j];
            hiR[j] = half ? xr[j]   : pr[j];
            hiI[j] = half ? xi[j]   : pimg[j];
        }

        float nxr[5], nxi[5];
#pragma unroll
        for (int i = 0; i < 5; i++) {
            float X = xr[i], Y = xi[i];
            // Horner polyval (sequential, unfused)
            float yr = pc[0], yi = 0.f;
#pragma unroll
            for (int m = 1; m <= 10; m++) {
                float tr = __fadd_rn(__fsub_rn(__fmul_rn(yr, X), __fmul_rn(yi, Y)), pc[m]);
                float ti = __fadd_rn(__fmul_rn(yr, Y), __fmul_rn(yi, X));
                yr = tr; yi = ti;
            }
            // prod over j = 0..9 in global order (eye adds 1 at my global index)
            float dr = 1.f, di = 0.f;
#pragma unroll
            for (int j = 0; j < 5; j++) {
                float eye = (half == 0 && i == j) ? 1.f : 0.f;
                float er = __fadd_rn(__fsub_rn(X, loR[j]), eye);
                float ei = __fsub_rn(Y, loI[j]);
                float tr = __fsub_rn(__fmul_rn(dr, er), __fmul_rn(di, ei));
                float ti = __fadd_rn(__fmul_rn(dr, ei), __fmul_rn(di, er));
                dr = tr; di = ti;
            }
#pragma unroll
            for (int j = 0; j < 5; j++) {
                float eye = (half == 1 && i == j) ? 1.f : 0.f;
                float er = __fadd_rn(__fsub_rn(X, hiR[j]), eye);
                float ei = __fsub_rn(Y, hiI[j]);
                float tr = __fsub_rn(__fmul_rn(dr, er), __fmul_rn(di, ei));
                float ti = __fadd_rn(__fmul_rn(dr, ei), __fmul_rn(di, er));
                dr = tr; di = ti;
            }
            dr = __fadd_rn(dr, 1e-12f);
            float qr, qi;
            cdivf(yr, yi, dr, di, qr, qi);
            nxr[i] = __fsub_rn(X, qr);
            nxi[i] = __fsub_rn(Y, qi);
        }
#pragma unroll
        for (int i = 0; i < 5; i++) { xr[i] = nxr[i]; xi[i] = nxi[i]; }
    }

    // ---- roots -> formants, exchange, sort, write (even lane) ----
    float f5[5];
#pragma unroll
    for (int i = 0; i < 5; i++) {
        float fr = atan2f(xi[i], xr[i]) * (10000.0f / (2.0f * (float)PI_D));
        bool valid = (xi[i] > 0.f) && (fr > 50.0f) && (fr < 4950.0f);
        f5[i] = valid ? fr : 10000.0f;
    }
    float pf[5];
#pragma unroll
    for (int j = 0; j < 5; j++) pf[j] = __shfl_xor_sync(FULLMASK, f5[j], 1);

    float f[10];
#pragma unroll
    for (int j = 0; j < 5; j++) {
        f[j]     = half ? pf[j] : f5[j];
        f[5 + j] = half ? f5[j] : pf[j];
    }
#pragma unroll
    for (int pass = 0; pass < 9; pass++) {
#pragma unroll
        for (int i = 0; i < 9; i++) {
            float lo = fminf(f[i], f[i + 1]);
            float hi = fmaxf(f[i], f[i + 1]);
            f[i] = lo; f[i + 1] = hi;
        }
    }

    if (half == 0) {
        int b = frame / T_DIM;
        int t = frame - b * T_DIM;
        float* ob = out + (size_t)b * (4 * T_DIM) + t;
#pragma unroll
        for (int q = 0; q < 4; q++)
            ob[q * T_DIM] = 2.0f * f[q] / 11025.0f - 1.0f;
    }
}

extern "C" void kernel_launch(void* const* d_in, const int* in_sizes, int n_in,
                              void* d_out, int out_size) {
    const float* in = (const float*)d_in[0];
    float* out = (float*)d_out;
    (void)in_sizes; (void)n_in; (void)out_size;

    init_consts_kernel<<<121, 128>>>();
    frontend_kernel<<<(NFRAMES + 127) / 128, 128>>>(in);
    dk_kernel<<<(NFRAMES * 2) / 256, 256>>>(out);
}

// round 10
// speedup vs baseline: 1.1508x; 1.1508x over previous
#include <cuda_runtime.h>
#include <math.h>

#define B_DIM 64
#define T_DIM 1000
#define P_ORD 10
#define NFRAMES (B_DIM * T_DIM)
#define PI_D 3.14159265358979323846
#define FULLMASK 0xffffffffu

__device__ double d_M[121];
__device__ float d_x0[20];

// Parallel init: one block per matrix entry (j,d); threads split the k-sum.
__global__ void init_consts_kernel() {
    __shared__ double red[128];
    int e = blockIdx.x;
    int j = e / 11, d = e % 11;
    int k = threadIdx.x;

    double term = 0.0;
    if (k >= 1 && k <= 114) {
        double gd = (d == 0) ? 1.0 : 2.0 * cos(2.0 * PI_D * (double)k * (double)d / 512.0);
        term = 2.0 * gd * cos(2.0 * PI_D * (double)k * (double)j / 230.0);
    }
    red[threadIdx.x] = term;
    __syncthreads();
#pragma unroll
    for (int s = 64; s > 0; s >>= 1) {
        if (threadIdx.x < s) red[threadIdx.x] += red[threadIdx.x + s];
        __syncthreads();
    }
    if (threadIdx.x == 0) {
        double s = red[0];
        s += (d == 0) ? 1.0 : 2.0;                               // k = 0 bin
        double g115 = (d == 0) ? 1.0 : 2.0 * cos(2.0 * PI_D * 115.0 * (double)d / 512.0);
        s += ((j & 1) ? -1.0 : 1.0) * g115;                      // k = 115 Nyquist
        d_M[e] = s / 230.0;
    }
    if (e == 0 && threadIdx.x == 127) {
        double cr = 1.0, ci = 0.0;
        for (int p = 0; p < 10; p++) {
            double nr = cr * 0.4 - ci * 0.9;
            double ni = cr * 0.9 + ci * 0.4;
            cr = nr; ci = ni;
            d_x0[p]      = (float)nr;
            d_x0[10 + p] = (float)ni;
        }
    }
}

// XLA-faithful complex division: Smith + __divsc3-style recovery, IEEE rn.
__device__ __forceinline__ void cdivf(float a, float b, float c, float d,
                                      float& outr, float& outi) {
    float re, im;
    if (fabsf(c) >= fabsf(d)) {
        float r     = __fdiv_rn(d, c);
        float denom = __fadd_rn(c, __fmul_rn(d, r));
        re = __fdiv_rn(__fadd_rn(a, __fmul_rn(b, r)), denom);
        im = __fdiv_rn(__fsub_rn(b, __fmul_rn(a, r)), denom);
    } else {
        float r     = __fdiv_rn(c, d);
        float denom = __fadd_rn(__fmul_rn(c, r), d);
        re = __fdiv_rn(__fadd_rn(__fmul_rn(a, r), b), denom);
        im = __fdiv_rn(__fsub_rn(__fmul_rn(b, r), a), denom);
    }
    if (isnan(re) && isnan(im)) {
        if ((c == 0.0f && d == 0.0f) && (!isnan(a) || !isnan(b))) {
            re = copysignf(INFINITY, c) * a;
            im = copysignf(INFINITY, c) * b;
        } else if ((isinf(a) || isinf(b)) && isfinite(c) && isfinite(d)) {
            float aa = copysignf(isinf(a) ? 1.0f : 0.0f, a);
            float bb = copysignf(isinf(b) ? 1.0f : 0.0f, b);
            re = INFINITY * __fadd_rn(__fmul_rn(aa, c), __fmul_rn(bb, d));
            im = INFINITY * __fsub_rn(__fmul_rn(bb, c), __fmul_rn(aa, d));
        } else if ((isinf(c) || isinf(d)) && isfinite(a) && isfinite(b)) {
            float cc = copysignf(isinf(c) ? 1.0f : 0.0f, c);
            float dd = copysignf(isinf(d) ? 1.0f : 0.0f, d);
            re = 0.0f * __fadd_rn(__fmul_rn(a, cc), __fmul_rn(b, dd));
            im = 0.0f * __fsub_rn(__fmul_rn(b, cc), __fmul_rn(a, dd));
        }
    }
    outr = re; outi = im;
}

// Fused kernel: two threads per frame. Even lane runs the fp64 front-end;
// DK runs 5 roots per thread with xor-shuffle exchange.
__global__ void __launch_bounds__(128, 7)
formant_kernel(const float* __restrict__ in, float* __restrict__ out) {
    __shared__ double sM[121];
    __shared__ float sX0[20];
    if (threadIdx.x < 121) sM[threadIdx.x] = d_M[threadIdx.x];
    if (threadIdx.x < 20)  sX0[threadIdx.x] = d_x0[threadIdx.x];
    __syncthreads();

    int gtid  = blockIdx.x * 128 + threadIdx.x;
    int frame = gtid >> 1;
    int half  = gtid & 1;                 // 0: roots 0-4, 1: roots 5-9
    int b = frame / T_DIM;
    int t = frame - b * T_DIM;
    const float* base = in + (size_t)b * (P_ORD * T_DIM) + t;

    // ======== FRONT-END (fp64, even lane only) ========
    float pc[11];
#pragma unroll
    for (int i = 0; i < 11; i++) pc[i] = 0.f;

    if (half == 0) {
        double A[11];
        A[0] = 1.0;
        {
            double a[10];
            a[0] = (double)base[0];
#pragma unroll
            for (int p = 1; p < 10; p++) {
                double k = (double)base[p * T_DIM];
                double na[10];
#pragma unroll
                for (int i = 0; i < p; i++) na[i] = a[i] + k * a[p - 1 - i];
#pragma unroll
                for (int i = 0; i < p; i++) a[i] = na[i];
                a[p] = k;
            }
#pragma unroll
            for (int i = 0; i < 10; i++) A[i + 1] = a[i];
        }

        double c[11];
#pragma unroll
        for (int d = 0; d < 11; d++) {
            double s = 0.0;
#pragma unroll
            for (int n = 0; n < 11 - d; n++) s = fma(A[n], A[n + d], s);
            c[d] = s;
        }

        double r[11];
#pragma unroll
        for (int j = 0; j < 11; j++) {
            double s = 0.0;
#pragma unroll
            for (int d = 0; d < 11; d++) s = fma(sM[j * 11 + d], c[d], s);
            r[j] = s;
        }

        pc[0] = 1.0f;
        {
            double a[10];
            double k0 = -r[1] / r[0];
            a[0] = k0;
            double err = r[0] * (1.0 - k0 * k0);
#pragma unroll
            for (int m = 1; m < 10; m++) {
                double acc = r[m + 1];
#pragma unroll
                for (int i = 0; i < m; i++) acc = fma(a[i], r[m - i], acc);
                double k = -acc / err;
                double na[10];
#pragma unroll
                for (int i = 0; i < m; i++) na[i] = a[i] + k * a[m - 1 - i];
#pragma unroll
                for (int i = 0; i < m; i++) a[i] = na[i];
                a[m] = k;
                err *= (1.0 - k * k);
            }
#pragma unroll
            for (int i = 0; i < 10; i++) pc[i + 1] = (float)a[i];
        }
    }
    // broadcast pc from even lane to its odd partner
#pragma unroll
    for (int i = 0; i < 11; i++) {
        float v = __shfl_xor_sync(FULLMASK, pc[i], 1);
        if (half) pc[i] = v;
    }

    // ======== DURAND-KERNER: 5 roots per thread, XLA-faithful fp32 ========
    float xr[5], xi[5];
#pragma unroll
    for (int i = 0; i < 5; i++) {
        xr[i] = sX0[half * 5 + i];
        xi[i] = sX0[10 + half * 5 + i];
    }

#pragma unroll 1
    for (int it = 0; it < 30; it++) {
        // fetch partner's current roots (10 shuffles)
        float pr[5], pimg[5];
#pragma unroll
        for (int j = 0; j < 5; j++) {
            pr[j]   = __shfl_xor_sync(FULLMASK, xr[j], 1);
            pimg[j] = __shfl_xor_sync(FULLMASK, xi[j], 1);
        }
        // global-ordered halves via SELs
        float loR[5], loI[5], hiR[5], hiI[5];
#pragma unroll
        for (int j = 0; j < 5; j++) {
            loR[j] = half ? pr[j]   : xr[j];
            loI[j] = half ? pimg[j] : xi[j];
            hiR[j] = half ? xr[j]   : pr[j];
            hiI[j] = half ? xi[j]   : pimg[j];
        }

        float nxr[5], nxi[5];
#pragma unroll
        for (int i = 0; i < 5; i++) {
            float X = xr[i], Y = xi[i];
            // Horner polyval; first step folded: y = 1*x + pc[1] == (X+pc[1], Y)
            float yr = __fadd_rn(X, pc[1]);
            float yi = Y;
#pragma unroll
            for (int m = 2; m <= 10; m++) {
                float tr = __fadd_rn(__fsub_rn(__fmul_rn(yr, X), __fmul_rn(yi, Y)), pc[m]);
                float ti = __fadd_rn(__fmul_rn(yr, Y), __fmul_rn(yi, X));
                yr = tr; yi = ti;
            }
            // prod over j = 0..9 in global order; first factor folded into (dr,di);
            // eye-add only at my own global index (off-diagonal +0 adds elided).
            float dr = __fsub_rn(X, loR[0]);
            if (i == 0 && half == 0) dr = __fadd_rn(dr, 1.f);
            float di = __fsub_rn(Y, loI[0]);
#pragma unroll
            for (int j = 1; j < 5; j++) {
                float er = __fsub_rn(X, loR[j]);
                if (i == j && half == 0) er = __fadd_rn(er, 1.f);
                float ei = __fsub_rn(Y, loI[j]);
                float tr = __fsub_rn(__fmul_rn(dr, er), __fmul_rn(di, ei));
                float ti = __fadd_rn(__fmul_rn(dr, ei), __fmul_rn(di, er));
                dr = tr; di = ti;
            }
#pragma unroll
            for (int j = 0; j < 5; j++) {
                float er = __fsub_rn(X, hiR[j]);
                if (i == j && half == 1) er = __fadd_rn(er, 1.f);
                float ei = __fsub_rn(Y, hiI[j]);
                float tr = __fsub_rn(__fmul_rn(dr, er), __fmul_rn(di, ei));
                float ti = __fadd_rn(__fmul_rn(dr, ei), __fmul_rn(di, er));
                dr = tr; di = ti;
            }
            dr = __fadd_rn(dr, 1e-12f);
            float qr, qi;
            cdivf(yr, yi, dr, di, qr, qi);
            nxr[i] = __fsub_rn(X, qr);
            nxi[i] = __fsub_rn(Y, qi);
        }
#pragma unroll
        for (int i = 0; i < 5; i++) { xr[i] = nxr[i]; xi[i] = nxi[i]; }
    }

    // ---- roots -> formants, exchange, sort, write (even lane) ----
    float f5[5];
#pragma unroll
    for (int i = 0; i < 5; i++) {
        float fr = atan2f(xi[i], xr[i]) * (10000.0f / (2.0f * (float)PI_D));
        bool valid = (xi[i] > 0.f) && (fr > 50.0f) && (fr < 4950.0f);
        f5[i] = valid ? fr : 10000.0f;
    }
    float pf[5];
#pragma unroll
    for (int j = 0; j < 5; j++) pf[j] = __shfl_xor_sync(FULLMASK, f5[j], 1);

    float f[10];
#pragma unroll
    for (int j = 0; j < 5; j++) {
        f[j]     = half ? pf[j] : f5[j];
        f[5 + j] = half ? f5[j] : pf[j];
    }
#pragma unroll
    for (int pass = 0; pass < 9; pass++) {
#pragma unroll
        for (int i = 0; i < 9; i++) {
            float lo = fminf(f[i], f[i + 1]);
            float hi = fmaxf(f[i], f[i + 1]);
            f[i] = lo; f[i + 1] = hi;
        }
    }

    if (half == 0) {
        float* ob = out + (size_t)b * (4 * T_DIM) + t;
#pragma unroll
        for (int q = 0; q < 4; q++)
            ob[q * T_DIM] = 2.0f * f[q] / 11025.0f - 1.0f;
    }
}

extern "C" void kernel_launch(void* const* d_in, const int* in_sizes, int n_in,
                              void* d_out, int out_size) {
    const float* in = (const float*)d_in[0];
    float* out = (float*)d_out;
    (void)in_sizes; (void)n_in; (void)out_size;

    init_consts_kernel<<<121, 128>>>();
    formant_kernel<<<(NFRAMES * 2) / 128, 128>>>(in, out);
}

// round 11
// speedup vs baseline: 1.7462x; 1.5173x over previous
#include <cuda_runtime.h>
#include <math.h>

#define B_DIM 64
#define T_DIM 1000
#define P_ORD 10
#define NFRAMES (B_DIM * T_DIM)
#define PI_D 3.14159265358979323846
#define FULLMASK 0xffffffffu

__device__ double d_M[121];
__device__ float d_x0[20];

// Parallel init: one block per matrix entry (j,d); threads split the k-sum.
__global__ void init_consts_kernel() {
    __shared__ double red[128];
    int e = blockIdx.x;
    int j = e / 11, d = e % 11;
    int k = threadIdx.x;

    double term = 0.0;
    if (k >= 1 && k <= 114) {
        double gd = (d == 0) ? 1.0 : 2.0 * cos(2.0 * PI_D * (double)k * (double)d / 512.0);
        term = 2.0 * gd * cos(2.0 * PI_D * (double)k * (double)j / 230.0);
    }
    red[threadIdx.x] = term;
    __syncthreads();
#pragma unroll
    for (int s = 64; s > 0; s >>= 1) {
        if (threadIdx.x < s) red[threadIdx.x] += red[threadIdx.x + s];
        __syncthreads();
    }
    if (threadIdx.x == 0) {
        double s = red[0];
        s += (d == 0) ? 1.0 : 2.0;                               // k = 0 bin
        double g115 = (d == 0) ? 1.0 : 2.0 * cos(2.0 * PI_D * 115.0 * (double)d / 512.0);
        s += ((j & 1) ? -1.0 : 1.0) * g115;                      // k = 115 Nyquist
        d_M[e] = s / 230.0;
    }
    if (e == 0 && threadIdx.x == 127) {
        double cr = 1.0, ci = 0.0;
        for (int p = 0; p < 10; p++) {
            double nr = cr * 0.4 - ci * 0.9;
            double ni = cr * 0.9 + ci * 0.4;
            cr = nr; ci = ni;
            d_x0[p]      = (float)nr;
            d_x0[10 + p] = (float)ni;
        }
    }
}

// Smith complex division + __divsc3-style recovery (overflow-safe like XLA's).
__device__ __forceinline__ void cdivf(float a, float b, float c, float d,
                                      float& outr, float& outi) {
    float re, im;
    if (fabsf(c) >= fabsf(d)) {
        float r     = __fdiv_rn(d, c);
        float denom = __fadd_rn(c, __fmul_rn(d, r));
        re = __fdiv_rn(__fadd_rn(a, __fmul_rn(b, r)), denom);
        im = __fdiv_rn(__fsub_rn(b, __fmul_rn(a, r)), denom);
    } else {
        float r     = __fdiv_rn(c, d);
        float denom = __fadd_rn(__fmul_rn(c, r), d);
        re = __fdiv_rn(__fadd_rn(__fmul_rn(a, r), b), denom);
        im = __fdiv_rn(__fsub_rn(__fmul_rn(b, r), a), denom);
    }
    if (isnan(re) && isnan(im)) {
        if ((c == 0.0f && d == 0.0f) && (!isnan(a) || !isnan(b))) {
            re = copysignf(INFINITY, c) * a;
            im = copysignf(INFINITY, c) * b;
        } else if ((isinf(a) || isinf(b)) && isfinite(c) && isfinite(d)) {
            float aa = copysignf(isinf(a) ? 1.0f : 0.0f, a);
            float bb = copysignf(isinf(b) ? 1.0f : 0.0f, b);
            re = INFINITY * __fadd_rn(__fmul_rn(aa, c), __fmul_rn(bb, d));
            im = INFINITY * __fsub_rn(__fmul_rn(bb, c), __fmul_rn(aa, d));
        } else if ((isinf(c) || isinf(d)) && isfinite(a) && isfinite(b)) {
            float cc = copysignf(isinf(c) ? 1.0f : 0.0f, c);
            float dd = copysignf(isinf(d) ? 1.0f : 0.0f, d);
            re = 0.0f * __fadd_rn(__fmul_rn(a, cc), __fmul_rn(b, dd));
            im = 0.0f * __fsub_rn(__fmul_rn(b, cc), __fmul_rn(a, dd));
        }
    }
    outr = re; outi = im;
}

// Fused kernel: two threads per frame. Even lane runs the fp64 front-end;
// DK runs 5 roots per thread, FMA-contracted, own-then-partner product order.
__global__ void __launch_bounds__(128, 7)
formant_kernel(const float* __restrict__ in, float* __restrict__ out) {
    __shared__ double sM[121];
    __shared__ float sX0[20];
    if (threadIdx.x < 121) sM[threadIdx.x] = d_M[threadIdx.x];
    if (threadIdx.x < 20)  sX0[threadIdx.x] = d_x0[threadIdx.x];
    __syncthreads();

    int gtid  = blockIdx.x * 128 + threadIdx.x;
    int frame = gtid >> 1;
    int half  = gtid & 1;                 // 0: roots 0-4, 1: roots 5-9
    int b = frame / T_DIM;
    int t = frame - b * T_DIM;
    const float* base = in + (size_t)b * (P_ORD * T_DIM) + t;

    // ======== FRONT-END (fp64, even lane only) ========
    float pc[11];
#pragma unroll
    for (int i = 0; i < 11; i++) pc[i] = 0.f;

    if (half == 0) {
        double A[11];
        A[0] = 1.0;
        {
            double a[10];
            a[0] = (double)base[0];
#pragma unroll
            for (int p = 1; p < 10; p++) {
                double k = (double)base[p * T_DIM];
                double na[10];
#pragma unroll
                for (int i = 0; i < p; i++) na[i] = a[i] + k * a[p - 1 - i];
#pragma unroll
                for (int i = 0; i < p; i++) a[i] = na[i];
                a[p] = k;
            }
#pragma unroll
            for (int i = 0; i < 10; i++) A[i + 1] = a[i];
        }

        double c[11];
#pragma unroll
        for (int d = 0; d < 11; d++) {
            double s = 0.0;
#pragma unroll
            for (int n = 0; n < 11 - d; n++) s = fma(A[n], A[n + d], s);
            c[d] = s;
        }

        double r[11];
#pragma unroll
        for (int j = 0; j < 11; j++) {
            double s = 0.0;
#pragma unroll
            for (int d = 0; d < 11; d++) s = fma(sM[j * 11 + d], c[d], s);
            r[j] = s;
        }

        pc[0] = 1.0f;
        {
            double a[10];
            double k0 = -r[1] / r[0];
            a[0] = k0;
            double err = r[0] * (1.0 - k0 * k0);
#pragma unroll
            for (int m = 1; m < 10; m++) {
                double acc = r[m + 1];
#pragma unroll
                for (int i = 0; i < m; i++) acc = fma(a[i], r[m - i], acc);
                double k = -acc / err;
                double na[10];
#pragma unroll
                for (int i = 0; i < m; i++) na[i] = a[i] + k * a[m - 1 - i];
#pragma unroll
                for (int i = 0; i < m; i++) a[i] = na[i];
                a[m] = k;
                err *= (1.0 - k * k);
            }
#pragma unroll
            for (int i = 0; i < 10; i++) pc[i + 1] = (float)a[i];
        }
    }
    // broadcast pc from even lane to its odd partner
#pragma unroll
    for (int i = 0; i < 11; i++) {
        float v = __shfl_xor_sync(FULLMASK, pc[i], 1);
        if (half) pc[i] = v;
    }

    // ======== DURAND-KERNER: 5 roots/thread, FMA-contracted ========
    float xr[5], xi[5];
#pragma unroll
    for (int i = 0; i < 5; i++) {
        xr[i] = sX0[half * 5 + i];
        xi[i] = sX0[10 + half * 5 + i];
    }

#pragma unroll 1
    for (int it = 0; it < 30; it++) {
        // fetch partner's current roots (10 shuffles)
        float pr[5], pimg[5];
#pragma unroll
        for (int j = 0; j < 5; j++) {
            pr[j]   = __shfl_xor_sync(FULLMASK, xr[j], 1);
            pimg[j] = __shfl_xor_sync(FULLMASK, xi[j], 1);
        }

        float nxr[5], nxi[5];
#pragma unroll
        for (int i = 0; i < 5; i++) {
            float X = xr[i], Y = xi[i];
            // Horner polyval; first step folded: y1 = (X + pc[1], Y)
            float yr = __fadd_rn(X, pc[1]);
            float yi = Y;
#pragma unroll
            for (int m = 2; m <= 10; m++) {
                float tr = __fmaf_rn(yr, X, __fmaf_rn(-yi, Y, pc[m]));
                float ti = __fmaf_rn(yr, Y, __fmul_rn(yi, X));
                yr = tr; yi = ti;
            }
            // denominator product: own roots first (eye at j==i), then partner's.
            // For j==i: er = X-X+1 = 1, ei = +0 -> factor is exactly (1,0); start there.
            float dr = 1.f, di = 0.f;
            bool started = false;
#pragma unroll
            for (int j = 0; j < 5; j++) {
                if (j == i) continue;               // identity factor, skip
                float er = __fsub_rn(X, xr[j]);
                float ei = __fsub_rn(Y, xi[j]);
                if (!started) { dr = er; di = ei; started = true; }
                else {
                    float tr = __fmaf_rn(dr, er, -__fmul_rn(di, ei));
                    float ti = __fmaf_rn(dr, ei,  __fmul_rn(di, er));
                    dr = tr; di = ti;
                }
            }
#pragma unroll
            for (int j = 0; j < 5; j++) {
                float er = __fsub_rn(X, pr[j]);
                float ei = __fsub_rn(Y, pimg[j]);
                float tr = __fmaf_rn(dr, er, -__fmul_rn(di, ei));
                float ti = __fmaf_rn(dr, ei,  __fmul_rn(di, er));
                dr = tr; di = ti;
            }
            dr = __fadd_rn(dr, 1e-12f);
            float qr, qi;
            cdivf(yr, yi, dr, di, qr, qi);
            nxr[i] = __fsub_rn(X, qr);
            nxi[i] = __fsub_rn(Y, qi);
        }
#pragma unroll
        for (int i = 0; i < 5; i++) { xr[i] = nxr[i]; xi[i] = nxi[i]; }
    }

    // ---- roots -> formants, exchange, sort, write (even lane) ----
    float f5[5];
#pragma unroll
    for (int i = 0; i < 5; i++) {
        float fr = atan2f(xi[i], xr[i]) * (10000.0f / (2.0f * (float)PI_D));
        bool valid = (xi[i] > 0.f) && (fr > 50.0f) && (fr < 4950.0f);
        f5[i] = valid ? fr : 10000.0f;
    }
    float pf[5];
#pragma unroll
    for (int j = 0; j < 5; j++) pf[j] = __shfl_xor_sync(FULLMASK, f5[j], 1);

    float f[10];
#pragma unroll
    for (int j = 0; j < 5; j++) {
        f[j]     = half ? pf[j] : f5[j];
        f[5 + j] = half ? f5[j] : pf[j];
    }
#pragma unroll
    for (int pass = 0; pass < 9; pass++) {
#pragma unroll
        for (int i = 0; i < 9; i++) {
            float lo = fminf(f[i], f[i + 1]);
            float hi = fmaxf(f[i], f[i + 1]);
            f[i] = lo; f[i + 1] = hi;
        }
    }

    if (half == 0) {
        float* ob = out + (size_t)b * (4 * T_DIM) + t;
#pragma unroll
        for (int q = 0; q < 4; q++)
            ob[q * T_DIM] = 2.0f * f[q] / 11025.0f - 1.0f;
    }
}

extern "C" void kernel_launch(void* const* d_in, const int* in_sizes, int n_in,
                              void* d_out, int out_size) {
    const float* in = (const float*)d_in[0];
    float* out = (float*)d_out;
    (void)in_sizes; (void)n_in; (void)out_size;

    init_consts_kernel<<<121, 128>>>();
    formant_kernel<<<(NFRAMES * 2) / 128, 128>>>(in, out);
}

// round 12
// speedup vs baseline: 2.1641x; 1.2394x over previous
#include <cuda_runtime.h>
#include <math.h>

#define B_DIM 64
#define T_DIM 1000
#define P_ORD 10
#define NFRAMES (B_DIM * T_DIM)
#define PI_D 3.14159265358979323846
#define FULLMASK 0xffffffffu

__device__ double d_M[121];
__device__ float d_x0[20];

// Parallel init: one block per matrix entry (j,d); threads split the k-sum.
__global__ void init_consts_kernel() {
    __shared__ double red[128];
    int e = blockIdx.x;
    int j = e / 11, d = e % 11;
    int k = threadIdx.x;

    double term = 0.0;
    if (k >= 1 && k <= 114) {
        double gd = (d == 0) ? 1.0 : 2.0 * cos(2.0 * PI_D * (double)k * (double)d / 512.0);
        term = 2.0 * gd * cos(2.0 * PI_D * (double)k * (double)j / 230.0);
    }
    red[threadIdx.x] = term;
    __syncthreads();
#pragma unroll
    for (int s = 64; s > 0; s >>= 1) {
        if (threadIdx.x < s) red[threadIdx.x] += red[threadIdx.x + s];
        __syncthreads();
    }
    if (threadIdx.x == 0) {
        double s = red[0];
        s += (d == 0) ? 1.0 : 2.0;                               // k = 0 bin
        double g115 = (d == 0) ? 1.0 : 2.0 * cos(2.0 * PI_D * 115.0 * (double)d / 512.0);
        s += ((j & 1) ? -1.0 : 1.0) * g115;                      // k = 115 Nyquist
        d_M[e] = s / 230.0;
    }
    if (e == 0 && threadIdx.x == 127) {
        double cr = 1.0, ci = 0.0;
        for (int p = 0; p < 10; p++) {
            double nr = cr * 0.4 - ci * 0.9;
            double ni = cr * 0.9 + ci * 0.4;
            cr = nr; ci = ni;
            d_x0[p]      = (float)nr;
            d_x0[10 + p] = (float)ni;
        }
    }
}

// Smith complex division, 2-divide form (ratio + reciprocal), FMA-contracted,
// with __divsc3-style recovery. Overflow-safe like XLA's lowering.
__device__ __forceinline__ void cdivf(float a, float b, float c, float d,
                                      float& outr, float& outi) {
    float re, im;
    if (fabsf(c) >= fabsf(d)) {
        float r     = __fdiv_rn(d, c);
        float denom = __fmaf_rn(d, r, c);
        float inv   = __fdiv_rn(1.0f, denom);
        re = __fmul_rn(__fmaf_rn(b, r, a), inv);
        im = __fmul_rn(__fmaf_rn(-a, r, b), inv);
    } else {
        float r     = __fdiv_rn(c, d);
        float denom = __fmaf_rn(c, r, d);
        float inv   = __fdiv_rn(1.0f, denom);
        re = __fmul_rn(__fmaf_rn(a, r, b), inv);
        im = __fmul_rn(__fmaf_rn(b, r, -a), inv);
    }
    if (isnan(re) && isnan(im)) {
        if ((c == 0.0f && d == 0.0f) && (!isnan(a) || !isnan(b))) {
            re = copysignf(INFINITY, c) * a;
            im = copysignf(INFINITY, c) * b;
        } else if ((isinf(a) || isinf(b)) && isfinite(c) && isfinite(d)) {
            float aa = copysignf(isinf(a) ? 1.0f : 0.0f, a);
            float bb = copysignf(isinf(b) ? 1.0f : 0.0f, b);
            re = INFINITY * __fadd_rn(__fmul_rn(aa, c), __fmul_rn(bb, d));
            im = INFINITY * __fsub_rn(__fmul_rn(bb, c), __fmul_rn(aa, d));
        } else if ((isinf(c) || isinf(d)) && isfinite(a) && isfinite(b)) {
            float cc = copysignf(isinf(c) ? 1.0f : 0.0f, c);
            float dd = copysignf(isinf(d) ? 1.0f : 0.0f, d);
            re = 0.0f * __fadd_rn(__fmul_rn(a, cc), __fmul_rn(b, dd));
            im = 0.0f * __fsub_rn(__fmul_rn(b, cc), __fmul_rn(a, dd));
        }
    }
    outr = re; outi = im;
}

// Fused kernel: two threads per frame. Even lane runs the fp64 front-end;
// DK runs 5 roots per thread, FMA-contracted, with bitwise-fixpoint early exit.
__global__ void __launch_bounds__(128, 7)
formant_kernel(const float* __restrict__ in, float* __restrict__ out) {
    __shared__ double sM[121];
    __shared__ float sX0[20];
    if (threadIdx.x < 121) sM[threadIdx.x] = d_M[threadIdx.x];
    if (threadIdx.x < 20)  sX0[threadIdx.x] = d_x0[threadIdx.x];
    __syncthreads();

    int gtid  = blockIdx.x * 128 + threadIdx.x;
    int frame = gtid >> 1;
    int half  = gtid & 1;                 // 0: roots 0-4, 1: roots 5-9
    int b = frame / T_DIM;
    int t = frame - b * T_DIM;
    const float* base = in + (size_t)b * (P_ORD * T_DIM) + t;

    // ======== FRONT-END (fp64, even lane only) ========
    float pc[11];
#pragma unroll
    for (int i = 0; i < 11; i++) pc[i] = 0.f;

    if (half == 0) {
        double A[11];
        A[0] = 1.0;
        {
            double a[10];
            a[0] = (double)base[0];
#pragma unroll
            for (int p = 1; p < 10; p++) {
                double k = (double)base[p * T_DIM];
                double na[10];
#pragma unroll
                for (int i = 0; i < p; i++) na[i] = a[i] + k * a[p - 1 - i];
#pragma unroll
                for (int i = 0; i < p; i++) a[i] = na[i];
                a[p] = k;
            }
#pragma unroll
            for (int i = 0; i < 10; i++) A[i + 1] = a[i];
        }

        double c[11];
#pragma unroll
        for (int d = 0; d < 11; d++) {
            double s = 0.0;
#pragma unroll
            for (int n = 0; n < 11 - d; n++) s = fma(A[n], A[n + d], s);
            c[d] = s;
        }

        double r[11];
#pragma unroll
        for (int j = 0; j < 11; j++) {
            double s = 0.0;
#pragma unroll
            for (int d = 0; d < 11; d++) s = fma(sM[j * 11 + d], c[d], s);
            r[j] = s;
        }

        pc[0] = 1.0f;
        {
            double a[10];
            double k0 = -r[1] / r[0];
            a[0] = k0;
            double err = r[0] * (1.0 - k0 * k0);
#pragma unroll
            for (int m = 1; m < 10; m++) {
                double acc = r[m + 1];
#pragma unroll
                for (int i = 0; i < m; i++) acc = fma(a[i], r[m - i], acc);
                double k = -acc / err;
                double na[10];
#pragma unroll
                for (int i = 0; i < m; i++) na[i] = a[i] + k * a[m - 1 - i];
#pragma unroll
                for (int i = 0; i < m; i++) a[i] = na[i];
                a[m] = k;
                err *= (1.0 - k * k);
            }
#pragma unroll
            for (int i = 0; i < 10; i++) pc[i + 1] = (float)a[i];
        }
    }
    // broadcast pc from even lane to its odd partner
#pragma unroll
    for (int i = 0; i < 11; i++) {
        float v = __shfl_xor_sync(FULLMASK, pc[i], 1);
        if (half) pc[i] = v;
    }

    // ======== DURAND-KERNER: 5 roots/thread, FMA-contracted, early exit ========
    float xr[5], xi[5];
#pragma unroll
    for (int i = 0; i < 5; i++) {
        xr[i] = sX0[half * 5 + i];
        xi[i] = sX0[10 + half * 5 + i];
    }

#pragma unroll 1
    for (int it = 0; it < 30; it++) {
        // fetch partner's current roots (10 shuffles)
        float pr[5], pimg[5];
#pragma unroll
        for (int j = 0; j < 5; j++) {
            pr[j]   = __shfl_xor_sync(FULLMASK, xr[j], 1);
            pimg[j] = __shfl_xor_sync(FULLMASK, xi[j], 1);
        }

        float nxr[5], nxi[5];
#pragma unroll
        for (int i = 0; i < 5; i++) {
            float X = xr[i], Y = xi[i];
            // Horner polyval; first step folded: y1 = (X + pc[1], Y)
            float yr = __fadd_rn(X, pc[1]);
            float yi = Y;
#pragma unroll
            for (int m = 2; m <= 10; m++) {
                float tr = __fmaf_rn(yr, X, __fmaf_rn(-yi, Y, pc[m]));
                float ti = __fmaf_rn(yr, Y, __fmul_rn(yi, X));
                yr = tr; yi = ti;
            }
            // denominator product: own roots (skip identity j==i), then partner's.
            float dr = 1.f, di = 0.f;
            bool started = false;
#pragma unroll
            for (int j = 0; j < 5; j++) {
                if (j == i) continue;               // identity factor, skip
                float er = __fsub_rn(X, xr[j]);
                float ei = __fsub_rn(Y, xi[j]);
                if (!started) { dr = er; di = ei; started = true; }
                else {
                    float tr = __fmaf_rn(dr, er, -__fmul_rn(di, ei));
                    float ti = __fmaf_rn(dr, ei,  __fmul_rn(di, er));
                    dr = tr; di = ti;
                }
            }
#pragma unroll
            for (int j = 0; j < 5; j++) {
                float er = __fsub_rn(X, pr[j]);
                float ei = __fsub_rn(Y, pimg[j]);
                float tr = __fmaf_rn(dr, er, -__fmul_rn(di, ei));
                float ti = __fmaf_rn(dr, ei,  __fmul_rn(di, er));
                dr = tr; di = ti;
            }
            dr = __fadd_rn(dr, 1e-12f);
            float qr, qi;
            cdivf(yr, yi, dr, di, qr, qi);
            nxr[i] = __fsub_rn(X, qr);
            nxi[i] = __fsub_rn(Y, qi);
        }

        // Bitwise-fixpoint early exit: if the entire warp's state is unchanged,
        // all remaining iterations are provably no-ops (deterministic map).
        bool same = true;
#pragma unroll
        for (int i = 0; i < 5; i++) {
            same = same && (__float_as_int(nxr[i]) == __float_as_int(xr[i]))
                        && (__float_as_int(nxi[i]) == __float_as_int(xi[i]));
        }
#pragma unroll
        for (int i = 0; i < 5; i++) { xr[i] = nxr[i]; xi[i] = nxi[i]; }
        if (__all_sync(FULLMASK, same)) break;
    }

    // ---- roots -> formants, exchange, sort, write (even lane) ----
    float f5[5];
#pragma unroll
    for (int i = 0; i < 5; i++) {
        float fr = atan2f(xi[i], xr[i]) * (10000.0f / (2.0f * (float)PI_D));
        bool valid = (xi[i] > 0.f) && (fr > 50.0f) && (fr < 4950.0f);
        f5[i] = valid ? fr : 10000.0f;
    }
    float pf[5];
#pragma unroll
    for (int j = 0; j < 5; j++) pf[j] = __shfl_xor_sync(FULLMASK, f5[j], 1);

    float f[10];
#pragma unroll
    for (int j = 0; j < 5; j++) {
        f[j]     = half ? pf[j] : f5[j];
        f[5 + j] = half ? f5[j] : pf[j];
    }
#pragma unroll
    for (int pass = 0; pass < 9; pass++) {
#pragma unroll
        for (int i = 0; i < 9; i++) {
            float lo = fminf(f[i], f[i + 1]);
            float hi = fmaxf(f[i], f[i + 1]);
            f[i] = lo; f[i + 1] = hi;
        }
    }

    if (half == 0) {
        float* ob = out + (size_t)b * (4 * T_DIM) + t;
#pragma unroll
        for (int q = 0; q < 4; q++)
            ob[q * T_DIM] = 2.0f * f[q] / 11025.0f - 1.0f;
    }
}

extern "C" void kernel_launch(void* const* d_in, const int* in_sizes, int n_in,
                              void* d_out, int out_size) {
    const float* in = (const float*)d_in[0];
    float* out = (float*)d_out;
    (void)in_sizes; (void)n_in; (void)out_size;

    init_consts_kernel<<<121, 128>>>();
    formant_kernel<<<(NFRAMES * 2) / 128, 128>>>(in, out);
}

// round 13
// speedup vs baseline: 2.3007x; 1.0631x over previous
#include <cuda_runtime.h>
#include <math.h>

#define B_DIM 64
#define T_DIM 1000
#define P_ORD 10
#define NFRAMES (B_DIM * T_DIM)
#define PI_D 3.14159265358979323846
#define FULLMASK 0xffffffffu

__device__ double d_M[121];
__device__ float d_x0[20];

// ---- packed f32x2 helpers (sm_100+) ----
typedef unsigned long long u64;
__device__ __forceinline__ u64 pk2(float lo, float hi) {
    u64 r; asm("mov.b64 %0, {%1, %2};" : "=l"(r) : "f"(lo), "f"(hi)); return r;
}
__device__ __forceinline__ u64 add2(u64 a, u64 b) {
    u64 r; asm("add.rn.f32x2 %0, %1, %2;" : "=l"(r) : "l"(a), "l"(b)); return r;
}
__device__ __forceinline__ u64 mul2(u64 a, u64 b) {
    u64 r; asm("mul.rn.f32x2 %0, %1, %2;" : "=l"(r) : "l"(a), "l"(b)); return r;
}
__device__ __forceinline__ u64 fma2(u64 a, u64 b, u64 c) {
    u64 r; asm("fma.rn.f32x2 %0, %1, %2, %3;" : "=l"(r) : "l"(a), "l"(b), "l"(c)); return r;
}
__device__ __forceinline__ float lo2(u64 v) { return __uint_as_float((unsigned)v); }
__device__ __forceinline__ float hi2(u64 v) { return __uint_as_float((unsigned)(v >> 32)); }
#define NEG1_2  0xBF800000BF800000ULL   /* (-1,-1) */
#define EYE_LO2 0x000000003F800000ULL   /* (1, 0)  */
#define EYE_HI2 0x3F80000000000000ULL   /* (0, 1)  */
// exact subtraction a-b via single-rounded fma(b, -1, a)
__device__ __forceinline__ u64 sub2(u64 a, u64 b) { return fma2(b, NEG1_2, a); }

// Parallel init: one block per matrix entry (j,d); threads split the k-sum.
__global__ void init_consts_kernel() {
    __shared__ double red[128];
    int e = blockIdx.x;
    int j = e / 11, d = e % 11;
    int k = threadIdx.x;

    double term = 0.0;
    if (k >= 1 && k <= 114) {
        double gd = (d == 0) ? 1.0 : 2.0 * cos(2.0 * PI_D * (double)k * (double)d / 512.0);
        term = 2.0 * gd * cos(2.0 * PI_D * (double)k * (double)j / 230.0);
    }
    red[threadIdx.x] = term;
    __syncthreads();
#pragma unroll
    for (int s = 64; s > 0; s >>= 1) {
        if (threadIdx.x < s) red[threadIdx.x] += red[threadIdx.x + s];
        __syncthreads();
    }
    if (threadIdx.x == 0) {
        double s = red[0];
        s += (d == 0) ? 1.0 : 2.0;                               // k = 0 bin
        double g115 = (d == 0) ? 1.0 : 2.0 * cos(2.0 * PI_D * 115.0 * (double)d / 512.0);
        s += ((j & 1) ? -1.0 : 1.0) * g115;                      // k = 115 Nyquist
        d_M[e] = s / 230.0;
    }
    if (e == 0 && threadIdx.x == 127) {
        double cr = 1.0, ci = 0.0;
        for (int p = 0; p < 10; p++) {
            double nr = cr * 0.4 - ci * 0.9;
            double ni = cr * 0.9 + ci * 0.4;
            cr = nr; ci = ni;
            d_x0[p]      = (float)nr;
            d_x0[10 + p] = (float)ni;
        }
    }
}

// Smith complex division with approx divides + __divsc3-style recovery.
__device__ __forceinline__ void cdivf(float a, float b, float c, float d,
                                      float& outr, float& outi) {
    float re, im;
    if (fabsf(c) >= fabsf(d)) {
        float r     = __fdividef(d, c);
        float denom = __fmaf_rn(d, r, c);
        float inv;  asm("rcp.approx.f32 %0, %1;" : "=f"(inv) : "f"(denom));
        re = __fmul_rn(__fmaf_rn(b, r, a), inv);
        im = __fmul_rn(__fmaf_rn(-a, r, b), inv);
    } else {
        float r     = __fdividef(c, d);
        float denom = __fmaf_rn(c, r, d);
        float inv;  asm("rcp.approx.f32 %0, %1;" : "=f"(inv) : "f"(denom));
        re = __fmul_rn(__fmaf_rn(a, r, b), inv);
        im = __fmul_rn(__fmaf_rn(b, r, -a), inv);
    }
    if (isnan(re) && isnan(im)) {
        if ((c == 0.0f && d == 0.0f) && (!isnan(a) || !isnan(b))) {
            re = copysignf(INFINITY, c) * a;
            im = copysignf(INFINITY, c) * b;
        } else if ((isinf(a) || isinf(b)) && isfinite(c) && isfinite(d)) {
            float aa = copysignf(isinf(a) ? 1.0f : 0.0f, a);
            float bb = copysignf(isinf(b) ? 1.0f : 0.0f, b);
            re = INFINITY * __fadd_rn(__fmul_rn(aa, c), __fmul_rn(bb, d));
            im = INFINITY * __fsub_rn(__fmul_rn(bb, c), __fmul_rn(aa, d));
        } else if ((isinf(c) || isinf(d)) && isfinite(a) && isfinite(b)) {
            float cc = copysignf(isinf(c) ? 1.0f : 0.0f, c);
            float dd = copysignf(isinf(d) ? 1.0f : 0.0f, d);
            re = 0.0f * __fadd_rn(__fmul_rn(a, cc), __fmul_rn(b, dd));
            im = 0.0f * __fsub_rn(__fmul_rn(b, cc), __fmul_rn(a, dd));
        }
    }
    outr = re; outi = im;
}

// Fused kernel: two threads per frame. Even lane runs the fp64 front-end;
// DK: 5 roots/thread as 2 packed f32x2 pairs + 1 scalar, early exit.
__global__ void __launch_bounds__(128, 7)
formant_kernel(const float* __restrict__ in, float* __restrict__ out) {
    __shared__ double sM[121];
    __shared__ float sX0[20];
    if (threadIdx.x < 121) sM[threadIdx.x] = d_M[threadIdx.x];
    if (threadIdx.x < 20)  sX0[threadIdx.x] = d_x0[threadIdx.x];
    __syncthreads();

    int gtid  = blockIdx.x * 128 + threadIdx.x;
    int frame = gtid >> 1;
    int half  = gtid & 1;                 // 0: roots 0-4, 1: roots 5-9
    int b = frame / T_DIM;
    int t = frame - b * T_DIM;
    const float* base = in + (size_t)b * (P_ORD * T_DIM) + t;

    // ======== FRONT-END (fp64, even lane only) ========
    float pc[11];
#pragma unroll
    for (int i = 0; i < 11; i++) pc[i] = 0.f;

    if (half == 0) {
        double A[11];
        A[0] = 1.0;
        {
            double a[10];
            a[0] = (double)base[0];
#pragma unroll
            for (int p = 1; p < 10; p++) {
                double k = (double)base[p * T_DIM];
                double na[10];
#pragma unroll
                for (int i = 0; i < p; i++) na[i] = a[i] + k * a[p - 1 - i];
#pragma unroll
                for (int i = 0; i < p; i++) a[i] = na[i];
                a[p] = k;
            }
#pragma unroll
            for (int i = 0; i < 10; i++) A[i + 1] = a[i];
        }

        double c[11];
#pragma unroll
        for (int d = 0; d < 11; d++) {
            double s = 0.0;
#pragma unroll
            for (int n = 0; n < 11 - d; n++) s = fma(A[n], A[n + d], s);
            c[d] = s;
        }

        double r[11];
#pragma unroll
        for (int j = 0; j < 11; j++) {
            double s = 0.0;
#pragma unroll
            for (int d = 0; d < 11; d++) s = fma(sM[j * 11 + d], c[d], s);
            r[j] = s;
        }

        pc[0] = 1.0f;
        {
            double a[10];
            double k0 = -r[1] / r[0];
            a[0] = k0;
            double err = r[0] * (1.0 - k0 * k0);
#pragma unroll
            for (int m = 1; m < 10; m++) {
                double acc = r[m + 1];
#pragma unroll
                for (int i = 0; i < m; i++) acc = fma(a[i], r[m - i], acc);
                double k = -acc / err;
                double na[10];
#pragma unroll
                for (int i = 0; i < m; i++) na[i] = a[i] + k * a[m - 1 - i];
#pragma unroll
                for (int i = 0; i < m; i++) a[i] = na[i];
                a[m] = k;
                err *= (1.0 - k * k);
            }
#pragma unroll
            for (int i = 0; i < 10; i++) pc[i + 1] = (float)a[i];
        }
    }
    // broadcast pc from even lane to its odd partner
#pragma unroll
    for (int i = 0; i < 11; i++) {
        float v = __shfl_xor_sync(FULLMASK, pc[i], 1);
        if (half) pc[i] = v;
    }

    // packed (splatted) coefficients for the paired Horner
    u64 pcs2[11];
#pragma unroll
    for (int i = 1; i < 11; i++) pcs2[i] = pk2(pc[i], pc[i]);

    // ======== DURAND-KERNER: 2 f32x2 pairs + 1 scalar root per thread ========
    float xr[5], xi[5];
#pragma unroll
    for (int i = 0; i < 5; i++) {
        xr[i] = sX0[half * 5 + i];
        xi[i] = sX0[10 + half * 5 + i];
    }

#pragma unroll 1
    for (int it = 0; it < 30; it++) {
        // fetch partner's current roots (10 shuffles)
        float pr[5], pimg[5];
#pragma unroll
        for (int j = 0; j < 5; j++) {
            pr[j]   = __shfl_xor_sync(FULLMASK, xr[j], 1);
            pimg[j] = __shfl_xor_sync(FULLMASK, xi[j], 1);
        }

        // pack own state: pair A = roots (0,1), pair B = roots (2,3); root 4 scalar
        u64 AX = pk2(xr[0], xr[1]), AY = pk2(xi[0], xi[1]);
        u64 BX = pk2(xr[2], xr[3]), BY = pk2(xi[2], xi[3]);
        float X4 = xr[4], Y4 = xi[4];

        // ---- Horner polyval (first step folded: y1 = x + pc[1]) ----
        u64 yrA = add2(AX, pcs2[1]), yiA = AY;
        u64 yrB = add2(BX, pcs2[1]), yiB = BY;
        float yr4 = __fadd_rn(X4, pc[1]), yi4 = Y4;
#pragma unroll
        for (int m = 2; m <= 10; m++) {
            u64 tA = fma2(mul2(yiA, AY), NEG1_2, fma2(yrA, AX, pcs2[m]));
            yiA = fma2(yrA, AY, mul2(yiA, AX));
            yrA = tA;
            u64 tB = fma2(mul2(yiB, BY), NEG1_2, fma2(yrB, BX, pcs2[m]));
            yiB = fma2(yrB, BY, mul2(yiB, BX));
            yrB = tB;
            float t4 = __fmaf_rn(yr4, X4, __fmaf_rn(-yi4, Y4, pc[m]));
            yi4 = __fmaf_rn(yr4, Y4, __fmul_rn(yi4, X4));
            yr4 = t4;
        }

        // ---- denominator product over all 10 roots, eye on own diagonal ----
        u64 drA = 0, diA = 0, drB = 0, diB = 0;
        float dr4 = 0.f, di4 = 0.f;
#pragma unroll
        for (int j = 0; j < 10; j++) {
            float R  = (j < 5) ? xr[j]     : pr[j - 5];
            float I  = (j < 5) ? xi[j]     : pimg[j - 5];
            u64 R2 = pk2(R, R), I2 = pk2(I, I);

            u64 erA = sub2(AX, R2);
            if (j == 0) erA = add2(erA, EYE_LO2);
            if (j == 1) erA = add2(erA, EYE_HI2);
            u64 eiA = sub2(AY, I2);

            u64 erB = sub2(BX, R2);
            if (j == 2) erB = add2(erB, EYE_LO2);
            if (j == 3) erB = add2(erB, EYE_HI2);
            u64 eiB = sub2(BY, I2);

            float er4 = __fsub_rn(X4, R);
            if (j == 4) er4 = __fadd_rn(er4, 1.f);
            float ei4 = __fsub_rn(Y4, I);

            if (j == 0) {
                drA = erA; diA = eiA;
                drB = erB; diB = eiB;
                dr4 = er4; di4 = ei4;
            } else {
                u64 tA = fma2(mul2(diA, eiA), NEG1_2, mul2(drA, erA));
                diA = fma2(drA, eiA, mul2(diA, erA));
                drA = tA;
                u64 tB = fma2(mul2(diB, eiB), NEG1_2, mul2(drB, erB));
                diB = fma2(drB, eiB, mul2(diB, erB));
                drB = tB;
                float t4 = __fmaf_rn(dr4, er4, -__fmul_rn(di4, ei4));
                di4 = __fmaf_rn(dr4, ei4, __fmul_rn(di4, er4));
                dr4 = t4;
            }
        }

        // ---- per-root Smith division + update ----
        float yrS[5], yiS[5], drS[5], diS[5];
        yrS[0] = lo2(yrA); yrS[1] = hi2(yrA); yrS[2] = lo2(yrB); yrS[3] = hi2(yrB); yrS[4] = yr4;
        yiS[0] = lo2(yiA); yiS[1] = hi2(yiA); yiS[2] = lo2(yiB); yiS[3] = hi2(yiB); yiS[4] = yi4;
        drS[0] = lo2(drA); drS[1] = hi2(drA); drS[2] = lo2(drB); drS[3] = hi2(drB); drS[4] = dr4;
        diS[0] = lo2(diA); diS[1] = hi2(diA); diS[2] = lo2(diB); diS[3] = hi2(diB); diS[4] = di4;

        bool same = true;
#pragma unroll
        for (int i = 0; i < 5; i++) {
            float dr = __fadd_rn(drS[i], 1e-12f);
            float qr, qi;
            cdivf(yrS[i], yiS[i], dr, diS[i], qr, qi);
            float nx = __fsub_rn(xr[i], qr);
            float ny = __fsub_rn(xi[i], qi);
            same = same && (__float_as_int(nx) == __float_as_int(xr[i]))
                        && (__float_as_int(ny) == __float_as_int(xi[i]));
            xr[i] = nx; xi[i] = ny;
        }
        // Bitwise fixpoint for whole warp -> remaining iterations are no-ops.
        if (__all_sync(FULLMASK, same)) break;
    }

    // ---- roots -> formants, exchange, sort, write (even lane) ----
    float f5[5];
#pragma unroll
    for (int i = 0; i < 5; i++) {
        float fr = atan2f(xi[i], xr[i]) * (10000.0f / (2.0f * (float)PI_D));
        bool valid = (xi[i] > 0.f) && (fr > 50.0f) && (fr < 4950.0f);
        f5[i] = valid ? fr : 10000.0f;
    }
    float pf[5];
#pragma unroll
    for (int j = 0; j < 5; j++) pf[j] = __shfl_xor_sync(FULLMASK, f5[j], 1);

    float f[10];
#pragma unroll
    for (int j = 0; j < 5; j++) {
        f[j]     = half ? pf[j] : f5[j];
        f[5 + j] = half ? f5[j] : pf[j];
    }
#pragma unroll
    for (int pass = 0; pass < 9; pass++) {
#pragma unroll
        for (int i = 0; i < 9; i++) {
            float lo = fminf(f[i], f[i + 1]);
            float hi = fmaxf(f[i], f[i + 1]);
            f[i] = lo; f[i + 1] = hi;
        }
    }

    if (half == 0) {
        float* ob = out + (size_t)b * (4 * T_DIM) + t;
#pragma unroll
        for (int q = 0; q < 4; q++)
            ob[q * T_DIM] = 2.0f * f[q] / 11025.0f - 1.0f;
    }
}

extern "C" void kernel_launch(void* const* d_in, const int* in_sizes, int n_in,
                              void* d_out, int out_size) {
    const float* in = (const float*)d_in[0];
    float* out = (float*)d_out;
    (void)in_sizes; (void)n_in; (void)out_size;

    init_consts_kernel<<<121, 128>>>();
    formant_kernel<<<(NFRAMES * 2) / 128, 128>>>(in, out);
}